// round 14
// baseline (speedup 1.0000x reference)
#include <cuda_runtime.h>
#include <math.h>

#define NT   256
#define BSUB 4
#define TT   128
#define DD   256
#define HW   128
#define NSTG 1016  // (TT-1)*2*4

typedef unsigned long long ull;

__device__ __forceinline__ float tanha(float x) {
    float y; asm("tanh.approx.f32 %0, %1;" : "=f"(y) : "f"(x)); return y;
}
#define FFMA2(acc, a, b) \
    asm("fma.rn.f32x2 %0, %1, %2, %3;" : "=l"(acc) : "l"(a), "l"(b), "l"(acc))
#define ADD2(d, a, b) \
    asm("add.rn.f32x2 %0, %1, %2;" : "=l"(d) : "l"(a), "l"(b))
#define PACK2(d, lo, hi) \
    asm("mov.b64 %0, {%1,%2};" : "=l"(d) : "f"(lo), "f"(hi))
#define UNPACK2(lo, hi, d) \
    asm("mov.b64 {%0,%1}, %2;" : "=f"(lo), "=f"(hi) : "l"(d))
#define BAR0() asm volatile("bar.sync 0, 256;" ::: "memory")
#define BAR1_SYNC() asm volatile("bar.sync 1, 256;" ::: "memory")
#define BAR1_ARRIVE() asm volatile("bar.arrive 1, 256;" ::: "memory")

__device__ __forceinline__ float interp_c(float t, const float* __restrict__ row) {
    int i = (int)ceilf(t);
    i = i < 1 ? 1 : (i > DD - 1 ? DD - 1 : i);
    float w = t - (float)(i - 1);
    w = fminf(fmaxf(w, 0.f), 1.f);
    return (1.f - w) * row[i - 1] + w * row[i];
}

// L2 partial GEMM over a k-slice of 4*NQ columns, 4 o per thread, 4 rows.
// Stores packed (o, o+64) f32x2 partials: pSd[row][kg][slot], slot = l + 32*m'.
template<int NQ>
__device__ __forceinline__ void l2_slice(
    const ull (*w2p)[2 * NQ],
    const float* __restrict__ h1r, ull* __restrict__ pSd,
    int kg, int kbase, int l)
{
    #pragma unroll
    for (int half = 0; half < 2; ++half) {
        ull accA[4] = {0ull, 0ull, 0ull, 0ull};
        ull accB[4] = {0ull, 0ull, 0ull, 0ull};
        const float* ra = h1r + (2 * half) * HW + kbase;
        const float* rb = ra + HW;
        #pragma unroll
        for (int kq = 0; kq < NQ; ++kq) {
            ulonglong2 ha = *reinterpret_cast<const ulonglong2*>(ra + 4 * kq);
            ulonglong2 hb = *reinterpret_cast<const ulonglong2*>(rb + 4 * kq);
            #pragma unroll
            for (int m = 0; m < 4; ++m) {
                FFMA2(accA[m], w2p[m][2 * kq],     ha.x);
                FFMA2(accA[m], w2p[m][2 * kq + 1], ha.y);
                FFMA2(accB[m], w2p[m][2 * kq],     hb.x);
                FFMA2(accB[m], w2p[m][2 * kq + 1], hb.y);
            }
        }
        float sA[4], sB[4];
        #pragma unroll
        for (int m = 0; m < 4; ++m) {
            float lo, hi;
            UNPACK2(lo, hi, accA[m]); sA[m] = lo + hi;
            UNPACK2(lo, hi, accB[m]); sB[m] = lo + hi;
        }
        ull pA0, pA1, pB0, pB1;
        PACK2(pA0, sA[0], sA[2]);   // (o=l,    o=l+64)
        PACK2(pA1, sA[1], sA[3]);   // (o=l+32, o=l+96)
        PACK2(pB0, sB[0], sB[2]);
        PACK2(pB1, sB[1], sB[3]);
        const int rowA = 2 * half, rowB = 2 * half + 1;
        pSd[rowA * 512 + kg * 64 + l]      = pA0;
        pSd[rowA * 512 + kg * 64 + l + 32] = pA1;
        pSd[rowB * 512 + kg * 64 + l]      = pB0;
        pSd[rowB * 512 + kg * 64 + l + 32] = pB1;
    }
}

__global__ __launch_bounds__(NT, 2)
void ode_kernel(const float* __restrict__ ts, const float* __restrict__ y0,
                const float* __restrict__ latent, const int* __restrict__ length,
                const float* __restrict__ dts, const float* __restrict__ dcs,
                const float* __restrict__ W1, const float* __restrict__ b1,
                const float* __restrict__ W2, const float* __restrict__ b2,
                const float* __restrict__ W3, const float* __restrict__ b3,
                float* __restrict__ out)
{
    extern __shared__ float sm[];
    ull*    w1v  = reinterpret_cast<ull*>(sm);          // [32][34] u64 (stride-padded)
    float2* tmW  = reinterpret_cast<float2*>(sm + 2176); // [1024] (tt, wgt)
    ull*    pSd  = reinterpret_cast<ull*>(sm + 4224);    // [4 r][8 kg][64 slots]
    float*  ctab = sm + 8320;                            // [4 r][1024]
    float*  W3t  = sm + 12416;                           // [128][9]
    float*  h1r  = sm + 13568;                           // [4][128]
    float*  tmS  = sm + 14080;                           // [1024] stg
    ull*    b2d  = reinterpret_cast<ull*>(sm + 15104);   // [64] (b2[o], b2[o+64])

    const int tid = threadIdx.x;
    const int l   = tid & 31;
    const int kg  = tid >> 5;
    const int r0  = blockIdx.x * BSUB;

    // ---- one-time setup ----
    for (int i = tid; i < 9 * HW; i += NT) {
        int oo = i >> 7, k = i & 127;
        W3t[k * 9 + oo] = W3[i];
    }
    for (int i = tid; i < 768; i += NT) {   // w1v[ll][nn][j], j<6
        int ll = i / 24, rem = i % 24;
        int nn = rem / 6, j = rem % 6;
        int o = 4 * ll + nn;
        const float* w = W1 + o * 43;
        float lo = 0.f, hi = 0.f;
        if (j < 4)      { lo = w[2 * j]; hi = w[2 * j + 1]; }
        else if (j == 4){ lo = w[8];     hi = w[41]; }
        ull p; PACK2(p, lo, hi);
        w1v[ll * 34 + nn * 6 + j] = p;
    }
    for (int g = tid; g < NSTG; g += NT) {  // time tables
        int n = g >> 3, sub = (g >> 2) & 1, s = g & 3;
        float t0v = ts[n];
        float dtf = (ts[n + 1] - t0v) * 0.5f;
        float tstart = t0v + (sub ? dtf : 0.f);
        float As = (s == 0) ? 0.f : ((s == 3) ? 1.f : 0.5f);
        float tt = tstart + As * dtf;
        float wgt = dtf * (1.f / 6.f) * ((s == 0 || s == 3) ? 1.f : 2.f);
        tmW[g] = make_float2(tt, wgt);
        tmS[g] = ((s == 2) ? 1.f : 0.5f) * dtf;
    }
    for (int i = tid; i < 4096; i += NT) {  // concentration table
        int r = i >> 10, g = i & 1023;
        if (g < NSTG) {
            int n = g >> 3, sub = (g >> 2) & 1, s = g & 3;
            float t0v = ts[n];
            float dtf = (ts[n + 1] - t0v) * 0.5f;
            float tstart = t0v + (sub ? dtf : 0.f);
            float As = (s == 0) ? 0.f : ((s == 3) ? 1.f : 0.5f);
            float tt = tstart + As * dtf;
            ctab[i] = interp_c(tt, dcs + (r0 + r) * DD);
        }
    }
    for (int k = tid; k < 64; k += NT) {
        ull p; PACK2(p, b2[k], b2[k + 64]);
        b2d[k] = p;
    }

    if (kg < BSUB) {
        // ================= ROW WARP (row r = kg) =================
        const int r = kg;
        ull w2p[4][4];                       // 8-k slice, kbase = 8*kg
        #pragma unroll
        for (int m = 0; m < 4; ++m) {
            const float* wr = W2 + (l + 32 * m) * HW + 8 * kg;
            #pragma unroll
            for (int kp = 0; kp < 4; ++kp) PACK2(w2p[m][kp], wr[2 * kp], wr[2 * kp + 1]);
        }
        ull wcbr[4];                         // (w_c, b1 + W1[:,9:41]·latent[r])
        #pragma unroll
        for (int nn = 0; nn < 4; ++nn) {
            int o = 4 * l + nn;
            const float* w = W1 + o * 43;
            float bp = b1[o];
            const float* lat = latent + (r0 + r) * 32;
            #pragma unroll
            for (int j = 0; j < 32; ++j) bp += w[9 + j] * lat[j];
            PACK2(wcbr[nn], w[42], bp);
        }
        ull b3p[4];
        #pragma unroll
        for (int j = 0; j < 4; ++j) PACK2(b3p[j], b3[2 * j], b3[2 * j + 1]);
        const float b3_8 = b3[8];

        ull ybase[4], yacc[4], ycur[4];
        #pragma unroll
        for (int j = 0; j < 4; ++j) { ybase[j] = 0ull; yacc[j] = 0ull; ycur[j] = 0ull; }
        float ybase8 = 0.f, yacc8 = 0.f, ycur8 = 0.f;
        int len = length[r0 + r];
        int idx = len - 1; if (idx < 0) idx = 0;
        const float tendr = ts[idx];
        float y0r = y0[r0 + r];
        if (l == 0) out[(r0 + r) * TT] = y0r;
        PACK2(ybase[0], y0r, 0.f);
        yacc[0] = ybase[0];
        ycur[0] = ybase[0];
        __syncthreads();

        #pragma unroll 1
        for (int g = 0; g < NSTG; ++g) {
            float2 tm = tmW[g];
            const float tt = tm.x, wgt = tm.y;

            // ---- layer 1: 4 neurons/lane, 3 LDS.128 weights each ----
            {
                float c = ctab[(r << 10) + g];
                ull ytt, c1;
                PACK2(ytt, ycur8, tt);
                PACK2(c1, c, 1.0f);
                float hq[4];
                #pragma unroll
                for (int nn = 0; nn < 4; ++nn) {
                    const ull* wb = w1v + l * 34 + nn * 6;
                    ulonglong2 A = *reinterpret_cast<const ulonglong2*>(wb);
                    ulonglong2 B = *reinterpret_cast<const ulonglong2*>(wb + 2);
                    ulonglong2 C = *reinterpret_cast<const ulonglong2*>(wb + 4);
                    ull acc = 0ull;
                    FFMA2(acc, A.x, ycur[0]);
                    FFMA2(acc, A.y, ycur[1]);
                    FFMA2(acc, B.x, ycur[2]);
                    FFMA2(acc, B.y, ycur[3]);
                    FFMA2(acc, C.x, ytt);
                    FFMA2(acc, wcbr[nn], c1);
                    float lo, hi; UNPACK2(lo, hi, acc);
                    hq[nn] = tanha(lo + hi);
                }
                *reinterpret_cast<float4*>(h1r + r * HW + 4 * l) =
                    make_float4(hq[0], hq[1], hq[2], hq[3]);
            }
            BAR0();

            l2_slice<2>(w2p, h1r, pSd, kg, 8 * kg, l);
            BAR1_SYNC();

            // ---- layer 3 + epilogue ----
            {
                float acc9[9];
                #pragma unroll
                for (int o2 = 0; o2 < 9; ++o2) acc9[o2] = 0.f;
                #pragma unroll
                for (int jj = 0; jj < 2; ++jj) {
                    const int slot = l + 32 * jj;
                    const ull* pb = pSd + r * 512 + slot;
                    ull t0v, t1v, t2v, t3v;
                    ADD2(t0v, pb[0],   pb[64]);
                    ADD2(t1v, pb[128], pb[192]);
                    ADD2(t2v, pb[256], pb[320]);
                    ADD2(t3v, pb[384], pb[448]);
                    ADD2(t0v, t0v, t1v);
                    ADD2(t2v, t2v, t3v);
                    ADD2(t0v, t0v, t2v);
                    ADD2(t0v, t0v, b2d[slot]);
                    float lo, hi; UNPACK2(lo, hi, t0v);
                    float hA = tanha(lo);          // o = slot
                    float hB = tanha(hi);          // o = slot + 64
                    const float* wA = W3t + slot * 9;
                    const float* wB = W3t + (slot + 64) * 9;
                    #pragma unroll
                    for (int o2 = 0; o2 < 9; ++o2)
                        acc9[o2] += hA * wA[o2] + hB * wB[o2];
                }
                // packed butterfly reduction
                ull p0, p1, p2, p3;
                PACK2(p0, acc9[0], acc9[1]);
                PACK2(p1, acc9[2], acc9[3]);
                PACK2(p2, acc9[4], acc9[5]);
                PACK2(p3, acc9[6], acc9[7]);
                float a8 = acc9[8];
                #pragma unroll
                for (int off = 16; off > 0; off >>= 1) {
                    ull s0 = __shfl_xor_sync(0xffffffffu, p0, off);
                    ull s1 = __shfl_xor_sync(0xffffffffu, p1, off);
                    ull s2 = __shfl_xor_sync(0xffffffffu, p2, off);
                    ull s3 = __shfl_xor_sync(0xffffffffu, p3, off);
                    a8 += __shfl_xor_sync(0xffffffffu, a8, off);
                    ADD2(p0, p0, s0);
                    ADD2(p1, p1, s1);
                    ADD2(p2, p2, s2);
                    ADD2(p3, p3, s3);
                }
                ADD2(p0, p0, b3p[0]);
                ADD2(p1, p1, b3p[1]);
                ADD2(p2, p2, b3p[2]);
                ADD2(p3, p3, b3p[3]);
                a8 += b3_8;
                {   // kv[0] = -cos(kv[0])
                    float lo, hi; UNPACK2(lo, hi, p0);
                    lo = -__cosf(lo);
                    PACK2(p0, lo, hi);
                }
                const bool stop = (tt > tendr);
                if (stop) { p0 = 0ull; p1 = 0ull; p2 = 0ull; p3 = 0ull; a8 = 0.f; }

                ull wg2; PACK2(wg2, wgt, wgt);
                FFMA2(yacc[0], wg2, p0);
                FFMA2(yacc[1], wg2, p1);
                FFMA2(yacc[2], wg2, p2);
                FFMA2(yacc[3], wg2, p3);
                yacc8 = fmaf(wgt, a8, yacc8);
                if ((g & 3) != 3) {
                    float stg = tmS[g];
                    ull st2; PACK2(st2, stg, stg);
                    ycur[0] = ybase[0]; FFMA2(ycur[0], st2, p0);
                    ycur[1] = ybase[1]; FFMA2(ycur[1], st2, p1);
                    ycur[2] = ybase[2]; FFMA2(ycur[2], st2, p2);
                    ycur[3] = ybase[3]; FFMA2(ycur[3], st2, p3);
                    ycur8 = fmaf(stg, a8, ybase8);
                } else {
                    #pragma unroll
                    for (int j = 0; j < 4; ++j) { ybase[j] = yacc[j]; ycur[j] = yacc[j]; }
                    ybase8 = yacc8; ycur8 = yacc8;
                    if ((g & 7) == 7 && l == 0) {
                        float yb, dum; UNPACK2(yb, dum, ybase[0]);
                        out[(r0 + r) * TT + (g >> 3) + 1] = yb;
                    }
                }
            }
        }
    } else {
        // ================= HELPER WARP (kg 4..7): 24-k slice =================
        const int kbase = 32 + 24 * (kg - 4);
        ull w2p[4][12];
        #pragma unroll
        for (int m = 0; m < 4; ++m) {
            const float* wr = W2 + (l + 32 * m) * HW + kbase;
            #pragma unroll
            for (int kp = 0; kp < 12; ++kp) PACK2(w2p[m][kp], wr[2 * kp], wr[2 * kp + 1]);
        }
        __syncthreads();
        #pragma unroll 1
        for (int g = 0; g < NSTG; ++g) {
            BAR0();
            l2_slice<6>(w2p, h1r, pSd, kg, kbase, l);
            BAR1_ARRIVE();
        }
    }
}

extern "C" void kernel_launch(void* const* d_in, const int* in_sizes, int n_in,
                              void* d_out, int out_size) {
    const float* ts     = (const float*)d_in[0];
    const float* y0     = (const float*)d_in[1];
    const float* latent = (const float*)d_in[2];
    const int*   length = (const int*)  d_in[3];
    const float* dts    = (const float*)d_in[4];
    const float* dcs    = (const float*)d_in[5];
    const float* W1     = (const float*)d_in[6];
    const float* b1     = (const float*)d_in[7];
    const float* W2     = (const float*)d_in[8];
    const float* b2     = (const float*)d_in[9];
    const float* W3     = (const float*)d_in[10];
    const float* b3     = (const float*)d_in[11];
    float* out = (float*)d_out;

    // floats: w1v 2176 + tmW 2048 + pSd 4096 + ctab 4096 + W3t 1152
    //         + h1r 512 + tmS 1024 + b2d 128 = 15232 (60928 B)
    const size_t smem = 15232 * sizeof(float);
    cudaFuncSetAttribute(ode_kernel, cudaFuncAttributeMaxDynamicSharedMemorySize, (int)smem);

    ode_kernel<<<256, NT, smem>>>(ts, y0, latent, length, dts, dcs,
                                  W1, b1, W2, b2, W3, b3, out);
}